// round 16
// baseline (speedup 1.0000x reference)
#include <cuda_runtime.h>
#include <math.h>

#define NN 100000
#define EE 1600000
#define DIN 32
#define DOUT 64
#define NPART 128
#define NCAND 32768
#define NTIE 512
#define NHC 16
#define NSEL 64

// ---------------- device scratch ----------------
__device__ float d_norm[NN];
__device__ int   d_off[NN + 1];
__device__ int   d_cur[NN];
__device__ int   d_csr_src[EE];
__device__ int   d_csr_eid[EE];
__device__ unsigned char d_wc[EE];
__device__ float2 d_scal0[NN];      // {norm, 1/||h||}
__device__ float2 d_scal1[NN];
__device__ float d_hA[NN * DIN];
__device__ float d_hB[NN * DIN];
__device__ unsigned d_keys[EE];
__device__ unsigned d_hist[NHC][65536];   // privatized histograms
__device__ unsigned d_binsum[65536];
__device__ unsigned d_rangeTot[NSEL];
__device__ unsigned short d_candKey[NCAND];
__device__ int d_candEid[NCAND];
__device__ int d_candPos[NCAND];

struct SelBlock {
    int deg[NN];
    unsigned long long state[NPART];
    unsigned bucket;
    unsigned R1;
    unsigned candCount;
    unsigned finCount;
};
__device__ SelBlock d_sb;

// ---------------- preprocessing ----------------

// degree count + zero the privatized histograms (spare threads)
__global__ void k_deg(const int* __restrict__ dst, int e_n) {
    int e = blockIdx.x * blockDim.x + threadIdx.x;
    if (e < NHC * 65536) ((unsigned*)d_hist)[e] = 0;
    if (e < e_n) atomicAdd(&d_sb.deg[dst[e]], 1);
}

// single-kernel exclusive scan via decoupled lookback
__global__ void k_scan(int n) {
    int bid = blockIdx.x;
    int i = bid * 1024 + threadIdx.x;
    int lane = threadIdx.x & 31, wid = threadIdx.x >> 5;
    int v = (i < n) ? d_sb.deg[i] : 0;
    int incl = v;
    #pragma unroll
    for (int o = 1; o < 32; o <<= 1) {
        int t = __shfl_up_sync(0xFFFFFFFFu, incl, o);
        if (lane >= o) incl += t;
    }
    __shared__ int ws[32];
    __shared__ int s_prefix, s_total;
    if (lane == 31) ws[wid] = incl;
    __syncthreads();
    if (wid == 0) {
        int wv = ws[lane];
        int wi = wv;
        #pragma unroll
        for (int o = 1; o < 32; o <<= 1) {
            int t = __shfl_up_sync(0xFFFFFFFFu, wi, o);
            if (lane >= o) wi += t;
        }
        ws[lane] = wi - wv;
        if (lane == 31) s_total = wi;
    }
    __syncthreads();
    int total = s_total;
    if (threadIdx.x == 0) {
        unsigned long long flag = (bid == 0) ? 2ull : 1ull;
        atomicExch(&d_sb.state[bid], (flag << 62) | (unsigned long long)(unsigned)total);
        int prefix = 0;
        if (bid > 0) {
            int j = bid - 1;
            while (1) {
                unsigned long long sf;
                do { sf = atomicAdd(&d_sb.state[j], 0ull); } while ((sf >> 62) == 0);
                prefix += (int)(unsigned)(sf & 0xFFFFFFFFull);
                if ((sf >> 62) == 2ull) break;
                j--;
            }
            atomicExch(&d_sb.state[bid], (2ull << 62) | (unsigned long long)(unsigned)(prefix + total));
        }
        s_prefix = prefix;
    }
    __syncthreads();
    int ex = s_prefix + ws[wid] + incl - v;
    if (i < n) {
        d_off[i] = ex;
        d_cur[i] = ex;
        d_norm[i] = rsqrtf((float)(v < 1 ? 1 : v));
    }
    if (i == n - 1) d_off[n] = ex + v;
}

// fused: CSR scatter (first gEblocks) + per-node scal0 (rest)
__global__ void k_build(const int* __restrict__ src, const int* __restrict__ dst,
                        const float* __restrict__ h, float2* __restrict__ scal,
                        int e_n, int n, int gEblocks) {
    if ((int)blockIdx.x < gEblocks) {
        int e = blockIdx.x * 256 + threadIdx.x;
        if (e < e_n) {
            int d = dst[e];
            int p = atomicAdd(&d_cur[d], 1);
            d_csr_src[p] = src[e];
            d_csr_eid[p] = e;
        }
    } else {
        int node = (blockIdx.x - gEblocks) * 8 + (threadIdx.x >> 5);
        int t = threadIdx.x & 31;
        if (node >= n) return;
        float v = h[node * DIN + t];
        float sq = v * v;
        #pragma unroll
        for (int o = 16; o; o >>= 1) sq += __shfl_xor_sync(0xFFFFFFFFu, sq, o);
        float l2 = fmaxf(sqrtf(sq), 1e-12f);
        if (t == 0) scal[node] = make_float2(d_norm[node], 1.0f / l2);
    }
}

// ---------------- hop kernels ----------------

// fused cosine keys + full (uncut) propagation sum (histogram moved out).
// warp per dst node; src indices preloaded in one coalesced load + shfl.
// NOTE: hout must NOT alias hin (gathered at arbitrary indices).
__global__ void k_cossum(const float* __restrict__ hin, const float2* __restrict__ scal,
                         float* __restrict__ hout, int n) {
    int node = blockIdx.x * 8 + (threadIdx.x >> 5);
    int t = threadIdx.x & 31;
    if (node >= n) return;
    int g = t >> 3, sub = t & 7;
    const float4* h4 = (const float4*)hin;
    float4 drow = h4[node * 8 + sub];
    float2 sd = __ldg(&scal[node]);
    int b = d_off[node], e2 = d_off[node + 1];
    int deg = e2 - b;
    int myidx = (t < deg) ? __ldg(&d_csr_src[b + t]) : 0;
    float4 acc = make_float4(0.f, 0.f, 0.f, 0.f);
    int nb32 = deg < 32 ? deg : 32;
    for (int j0 = 0; j0 < nb32; j0 += 8) {
        int jA = j0 + g, jB = j0 + 4 + g;
        bool vA = jA < nb32, vB = jB < nb32;
        int sA = __shfl_sync(0xFFFFFFFFu, myidx, jA & 31);
        int sB = __shfl_sync(0xFFFFFFFFu, myidx, jB & 31);
        float4 aA = make_float4(0.f,0.f,0.f,0.f), aB = make_float4(0.f,0.f,0.f,0.f);
        float2 cA = make_float2(0.f,0.f), cB = make_float2(0.f,0.f);
        if (vA) { cA = __ldg(&scal[sA]); aA = h4[sA * 8 + sub]; }
        if (vB) { cB = __ldg(&scal[sB]); aB = h4[sB * 8 + sub]; }
        float pA = aA.x * drow.x + aA.y * drow.y + aA.z * drow.z + aA.w * drow.w;
        float pB = aB.x * drow.x + aB.y * drow.y + aB.z * drow.z + aB.w * drow.w;
        acc.x += cA.x * aA.x + cB.x * aB.x;
        acc.y += cA.x * aA.y + cB.x * aB.y;
        acc.z += cA.x * aA.z + cB.x * aB.z;
        acc.w += cA.x * aA.w + cB.x * aB.w;
        #pragma unroll
        for (int o = 1; o <= 4; o <<= 1) {
            pA += __shfl_xor_sync(0xFFFFFFFFu, pA, o);
            pB += __shfl_xor_sync(0xFFFFFFFFu, pB, o);
        }
        if (sub == 0 && vA) {
            float cos = pA * cA.y * sd.y;
            unsigned bits = __float_as_uint(cos);
            d_keys[b + jA] = (bits & 0x80000000u) ? ~bits : (bits | 0x80000000u);
        }
        if (sub == 4 && vB) {
            float cos = pB * cB.y * sd.y;
            unsigned bits = __float_as_uint(cos);
            d_keys[b + jB] = (bits & 0x80000000u) ? ~bits : (bits | 0x80000000u);
        }
    }
    // rare tail: deg > 32
    for (int k0 = b + 32; k0 < e2; k0 += 4) {
        int k = k0 + g;
        bool v = k < e2;
        int s = v ? __ldg(&d_csr_src[k]) : 0;
        float4 a = make_float4(0.f,0.f,0.f,0.f);
        float2 c = make_float2(0.f,0.f);
        if (v) { c = __ldg(&scal[s]); a = h4[s * 8 + sub]; }
        float p = a.x * drow.x + a.y * drow.y + a.z * drow.z + a.w * drow.w;
        acc.x += c.x * a.x; acc.y += c.x * a.y; acc.z += c.x * a.z; acc.w += c.x * a.w;
        #pragma unroll
        for (int o = 1; o <= 4; o <<= 1) p += __shfl_xor_sync(0xFFFFFFFFu, p, o);
        if (sub == 0 && v) {
            float cos = p * c.y * sd.y;
            unsigned bits = __float_as_uint(cos);
            d_keys[k] = (bits & 0x80000000u) ? ~bits : (bits | 0x80000000u);
        }
    }
    #pragma unroll
    for (int o = 8; o <= 16; o <<= 1) {
        acc.x += __shfl_xor_sync(0xFFFFFFFFu, acc.x, o);
        acc.y += __shfl_xor_sync(0xFFFFFFFFu, acc.y, o);
        acc.z += __shfl_xor_sync(0xFFFFFFFFu, acc.z, o);
        acc.w += __shfl_xor_sync(0xFFFFFFFFu, acc.w, o);
    }
    if (g == 0) {
        float nv = sd.x;
        ((float4*)hout)[node * 8 + sub] =
            make_float4(nv * acc.x, nv * acc.y, nv * acc.z, nv * acc.w);
    }
}

// level-1 histogram over keys: uint4 coalesced reads, NHC-privatized,
// warp-aggregated atomics (match_any)
__global__ void k_hist1(int e_n) {
    int i = blockIdx.x * blockDim.x + threadIdx.x;
    int e0 = i * 4;
    unsigned* hist = d_hist[blockIdx.x & (NHC - 1)];
    int lane = threadIdx.x & 31;
    int valid = (e0 + 3 < e_n);
    unsigned mask = __ballot_sync(0xFFFFFFFFu, valid);
    if (valid) {
        uint4 kk = ((const uint4*)d_keys)[i];
        unsigned b0 = kk.x >> 16, b1 = kk.y >> 16, b2 = kk.z >> 16, b3 = kk.w >> 16;
        unsigned p;
        p = __match_any_sync(mask, b0);
        if ((int)(__ffs(p) - 1) == lane) atomicAdd(&hist[b0], __popc(p));
        p = __match_any_sync(mask, b1);
        if ((int)(__ffs(p) - 1) == lane) atomicAdd(&hist[b1], __popc(p));
        p = __match_any_sync(mask, b2);
        if ((int)(__ffs(p) - 1) == lane) atomicAdd(&hist[b2], __popc(p));
        p = __match_any_sync(mask, b3);
        if ((int)(__ffs(p) - 1) == lane) atomicAdd(&hist[b3], __popc(p));
    } else {
        for (int e = e0; e < e_n; e++)
            atomicAdd(&hist[d_keys[e] >> 16], 1u);
    }
}

// distributed bucket selection: NSEL blocks sum hist copies; last block finishes.
__global__ void k_select0(unsigned kcut) {
    __shared__ unsigned ws[32];
    __shared__ unsigned s_isLast;
    int tid = threadIdx.x;
    int bid = blockIdx.x;
    int bin = bid * 1024 + tid;
    int lane = tid & 31, wid = tid >> 5;

    unsigned s = 0;
    #pragma unroll
    for (int c = 0; c < NHC; c++) s += d_hist[c][bin];
    d_binsum[bin] = s;

    unsigned r = s;
    #pragma unroll
    for (int o = 16; o; o >>= 1) r += __shfl_xor_sync(0xFFFFFFFFu, r, o);
    if (lane == 0) ws[wid] = r;
    __syncthreads();
    if (wid == 0) {
        unsigned q = ws[lane];
        #pragma unroll
        for (int o = 16; o; o >>= 1) q += __shfl_xor_sync(0xFFFFFFFFu, q, o);
        if (lane == 0) {
            d_rangeTot[bid] = q;
            __threadfence();
            unsigned c = atomicAdd(&d_sb.finCount, 1u);
            s_isLast = (c == NSEL - 1) ? 1u : 0u;
        }
    }
    __syncthreads();
    if (!s_isLast) return;

    if (tid == 0) d_sb.finCount = 0;
    __shared__ unsigned rt[NSEL];
    __shared__ int s_range;
    __shared__ unsigned s_target;
    if (tid < NSEL) rt[tid] = d_rangeTot[tid];
    __syncthreads();
    if (tid == 0) {
        unsigned cum = 0;
        for (int q = 0; q < NSEL; q++) {
            unsigned v = rt[q];
            if (kcut <= cum + v) { s_range = q; s_target = kcut - cum; break; }
            cum += v;
        }
    }
    __syncthreads();
    int rng = s_range;
    unsigned target = s_target;
    unsigned v = d_binsum[rng * 1024 + tid];
    unsigned incl = v;
    #pragma unroll
    for (int o = 1; o < 32; o <<= 1) {
        unsigned x = __shfl_up_sync(0xFFFFFFFFu, incl, o);
        if (lane >= o) incl += x;
    }
    __syncthreads();
    if (lane == 31) ws[wid] = incl;
    __syncthreads();
    if (wid == 0) {
        unsigned wv = ws[lane];
        unsigned wi = wv;
        #pragma unroll
        for (int o = 1; o < 32; o <<= 1) {
            unsigned x = __shfl_up_sync(0xFFFFFFFFu, wi, o);
            if (lane >= o) wi += x;
        }
        ws[lane] = wi - wv;
    }
    __syncthreads();
    unsigned inclT = ws[wid] + incl;
    unsigned exclT = inclT - v;
    if (v > 0 && exclT < target && target <= inclT) {
        d_sb.bucket = (unsigned)(rng * 1024 + tid);
        d_sb.R1 = target - exclT;
    }
}

// coalesced weight write + warp-aggregated candidate collection + hist re-zero
__global__ void k_markc(int e_n) {
    int k = blockIdx.x * blockDim.x + threadIdx.x;
    if (k < NHC * 65536) ((unsigned*)d_hist)[k] = 0;
    if (k >= e_n) return;
    unsigned key = d_keys[k];
    unsigned bkt = key >> 16;
    unsigned B = d_sb.bucket;
    d_wc[k] = (bkt < B) ? 0 : 1;
    bool cand = (bkt == B);
    unsigned m = __ballot_sync(0xFFFFFFFFu, cand);
    if (cand) {
        int lane = threadIdx.x & 31;
        int leader = __ffs(m) - 1;
        unsigned base = 0;
        if (lane == leader) base = atomicAdd(&d_sb.candCount, (unsigned)__popc(m));
        base = __shfl_sync(m, base, leader);
        unsigned q = base + __popc(m & ((1u << lane) - 1u));
        if (q < NCAND) {
            d_candKey[q] = (unsigned short)(key & 0xFFFFu);
            d_candEid[q] = d_csr_eid[k];
            d_candPos[q] = k;
        }
    }
}

// exact selection among candidates: 8+8 bit radix + deterministic eid tie-break
__global__ void k_fselect() {
    __shared__ unsigned hA[256], hB[256];
    __shared__ int s_b1, s_Rp, s_b0, s_Rpp;
    __shared__ int s_tieEid[NTIE], s_tiePos[NTIE];
    __shared__ unsigned s_tcnt;
    int tid = threadIdx.x;
    unsigned M = d_sb.candCount; if (M > NCAND) M = NCAND;
    unsigned R = d_sb.R1;
    for (int i = tid; i < 256; i += 1024) { hA[i] = 0; hB[i] = 0; }
    if (tid == 0) s_tcnt = 0;
    __syncthreads();
    for (unsigned i = tid; i < M; i += 1024)
        atomicAdd(&hA[d_candKey[i] >> 8], 1u);
    __syncthreads();
    if (tid == 0) {
        unsigned cum = 0;
        for (int k = 0; k < 256; k++) {
            unsigned v = hA[k];
            if (R <= cum + v) { s_b1 = k; s_Rp = (int)(R - cum); break; }
            cum += v;
        }
    }
    __syncthreads();
    unsigned b1 = (unsigned)s_b1;
    for (unsigned i = tid; i < M; i += 1024) {
        unsigned kk = d_candKey[i];
        if ((kk >> 8) == b1) atomicAdd(&hB[kk & 0xFFu], 1u);
    }
    __syncthreads();
    if (tid == 0) {
        unsigned cum = 0, Rp = (unsigned)s_Rp;
        for (int k = 0; k < 256; k++) {
            unsigned v = hB[k];
            if (Rp <= cum + v) { s_b0 = k; s_Rpp = (int)(Rp - cum); break; }
            cum += v;
        }
    }
    __syncthreads();
    unsigned Tlow = (b1 << 8) | (unsigned)s_b0;
    for (unsigned i = tid; i < M; i += 1024) {
        unsigned kk = d_candKey[i];
        if (kk < Tlow) d_wc[d_candPos[i]] = 0;
        else if (kk == Tlow) {
            unsigned q = atomicAdd(&s_tcnt, 1u);
            if (q < NTIE) { s_tieEid[q] = d_candEid[i]; s_tiePos[q] = d_candPos[i]; }
        }
    }
    __syncthreads();
    unsigned tc = s_tcnt; if (tc > NTIE) tc = NTIE;
    unsigned Rpp = (unsigned)s_Rpp;
    for (unsigned i = tid; i < tc; i += 1024) {
        int ei = s_tieEid[i];
        unsigned rank = 0;
        for (unsigned j = 0; j < tc; j++) rank += (unsigned)(s_tieEid[j] < ei);
        if (rank < Rpp) d_wc[s_tiePos[i]] = 0;
    }
    if (tid == 0) d_sb.candCount = 0;
}

// subtract cut-edge contributions; optionally emit next hop's scal
template <bool WRITE_SCAL>
__global__ void k_correct(float* __restrict__ h_io, const float* __restrict__ h_in,
                          const float2* __restrict__ scal_in, float2* __restrict__ scal_out,
                          int n) {
    int node = blockIdx.x * 8 + (threadIdx.x >> 5);
    int t = threadIdx.x & 31;
    if (node >= n) return;
    int g = t >> 3, sub = t & 7;
    int b = d_off[node], e2 = d_off[node + 1];
    const float4* h4 = (const float4*)h_in;
    float4 acc = make_float4(0.f, 0.f, 0.f, 0.f);
    for (int base = b; base < e2; base += 32) {
        int idx = base + t;
        unsigned char w = (idx < e2) ? d_wc[idx] : 1;
        unsigned m = __ballot_sync(0xFFFFFFFFu, w == 0);
        int nc = __popc(m);
        for (int q = g; q < nc; q += 4) {
            int j = (int)__fns(m, 0, q + 1);
            int k = base + j;
            int s = __ldg(&d_csr_src[k]);
            float c = __ldg(&scal_in[s]).x;
            float4 a = h4[s * 8 + sub];
            acc.x += c * a.x; acc.y += c * a.y; acc.z += c * a.z; acc.w += c * a.w;
        }
    }
    #pragma unroll
    for (int o = 8; o <= 16; o <<= 1) {
        acc.x += __shfl_xor_sync(0xFFFFFFFFu, acc.x, o);
        acc.y += __shfl_xor_sync(0xFFFFFFFFu, acc.y, o);
        acc.z += __shfl_xor_sync(0xFFFFFFFFu, acc.z, o);
        acc.w += __shfl_xor_sync(0xFFFFFFFFu, acc.w, o);
    }
    float nv = d_norm[node];
    float4 hv = make_float4(0.f, 0.f, 0.f, 0.f);
    if (g == 0) {
        hv = ((float4*)h_io)[node * 8 + sub];
        hv.x -= nv * acc.x; hv.y -= nv * acc.y; hv.z -= nv * acc.z; hv.w -= nv * acc.w;
        ((float4*)h_io)[node * 8 + sub] = hv;
    }
    if (WRITE_SCAL) {
        float sq = (g == 0) ? (hv.x*hv.x + hv.y*hv.y + hv.z*hv.z + hv.w*hv.w) : 0.f;
        #pragma unroll
        for (int o = 1; o <= 4; o <<= 1) sq += __shfl_xor_sync(0xFFFFFFFFu, sq, o);
        float l2 = fmaxf(sqrtf(sq), 1e-12f);
        if (t == 0) scal_out[node] = make_float2(nv, 1.0f / l2);
    }
}

__global__ void k_fc(const float* __restrict__ h, const float* __restrict__ W,
                     float* __restrict__ out, int n) {
    __shared__ float sW[DIN * DOUT];
    __shared__ float sh[16 * DIN];
    for (int i = threadIdx.x; i < DIN * DOUT; i += blockDim.x) {
        int j = i >> 5, t = i & 31;
        sW[t * DOUT + j] = W[i];
    }
    int row0 = blockIdx.x * 16;
    for (int i = threadIdx.x; i < 16 * DIN; i += blockDim.x) {
        int r = row0 + (i >> 5);
        sh[i] = (r < n) ? h[row0 * DIN + i] : 0.0f;
    }
    __syncthreads();
    int r = threadIdx.x >> 6;
    int j = threadIdx.x & 63;
    int row = row0 + r;
    if (row >= n) return;
    float acc = 0.0f;
    #pragma unroll
    for (int t = 0; t < DIN; t++) acc += sh[r * DIN + t] * sW[t * DOUT + j];
    out[row * DOUT + j] = acc;
}

// ---------------- launch ----------------

extern "C" void kernel_launch(void* const* d_in, const int* in_sizes, int n_in,
                              void* d_out, int out_size) {
    const float* features = (const float*)d_in[0];
    const int*   src      = (const int*)d_in[1];
    const int*   dst      = (const int*)d_in[2];
    const float* W        = (const float*)d_in[3];
    float* out = (float*)d_out;

    int n = in_sizes[0] / DIN;
    int e = in_sizes[1];
    if (n > NN) n = NN;
    if (e > EE) e = EE;
    unsigned kcut = (unsigned)((long long)e / 10);

    void *p_sb, *p_hA, *p_hB, *p_s0, *p_s1;
    cudaGetSymbolAddress(&p_sb, d_sb);
    cudaGetSymbolAddress(&p_hA, d_hA);
    cudaGetSymbolAddress(&p_hB, d_hB);
    cudaGetSymbolAddress(&p_s0, d_scal0);
    cudaGetSymbolAddress(&p_s1, d_scal1);

    float* hA = (float*)p_hA;
    float* hB = (float*)p_hB;
    float2* s0 = (float2*)p_s0;
    float2* s1 = (float2*)p_s1;

    int gE  = (e + 255) / 256;
    int gE4 = (e / 4 + 255) / 256;
    int gNw = (n + 7) / 8;
    int nb  = (n + 1023) / 1024;

    cudaMemsetAsync(p_sb, 0, sizeof(SelBlock));
    k_deg<<<gE, 256>>>(dst, e);
    k_scan<<<nb, 1024>>>(n);
    k_build<<<gE + gNw, 256>>>(src, dst, features, s0, e, n, gE);

    // hop 0 (k_cossum stays in profiled slot 5)
    k_cossum<<<gNw, 256>>>(features, s0, hA, n);
    k_hist1<<<gE4, 256>>>(e);
    k_select0<<<NSEL, 1024>>>(kcut);
    k_markc<<<gE, 256>>>(e);
    k_fselect<<<1, 1024>>>();
    k_correct<true><<<gNw, 256>>>(hA, features, s0, s1, n);

    // hop 1
    k_cossum<<<gNw, 256>>>(hA, s1, hB, n);
    k_hist1<<<gE4, 256>>>(e);
    k_select0<<<NSEL, 1024>>>(kcut);
    k_markc<<<gE, 256>>>(e);
    k_fselect<<<1, 1024>>>();
    k_correct<false><<<gNw, 256>>>(hB, hA, s1, nullptr, n);

    k_fc<<<(n + 15) / 16, 1024>>>(hB, W, out, n);
}

// round 17
// speedup vs baseline: 1.5516x; 1.5516x over previous
#include <cuda_runtime.h>
#include <math.h>

#define NN 100000
#define EE 1600000
#define DIN 32
#define DOUT 64
#define NPART 128
#define NCAND 32768
#define NTIE 512
#define NHC 16
#define NSEL 64

// ---------------- device scratch ----------------
__device__ float d_norm[NN];
__device__ int   d_off[NN + 1];
__device__ int   d_cur[NN];
__device__ int   d_csr_src[EE];
__device__ int   d_csr_eid[EE];
__device__ unsigned char d_wc[EE];
__device__ float2 d_scal0[NN];      // {norm, 1/||h||}
__device__ float2 d_scal1[NN];
__device__ float d_hA[NN * DIN];
__device__ float d_hB[NN * DIN];
__device__ unsigned d_keys[EE];
__device__ unsigned d_hist[NHC][65536];   // privatized histograms
__device__ unsigned d_binsum[65536];
__device__ unsigned d_rangeTot[NSEL];
__device__ unsigned short d_candKey[NCAND];
__device__ int d_candEid[NCAND];
__device__ int d_candPos[NCAND];

struct SelBlock {
    int deg[NN];
    unsigned long long state[NPART];
    unsigned bucket;
    unsigned R1;
    unsigned candCount;
    unsigned finCount;
};
__device__ SelBlock d_sb;

// ---------------- preprocessing ----------------

// edge blocks: zero hists + degree atomics. node blocks: scal0.y = 1/||h||
// (depends only on features, so it overlaps the degree pass).
__global__ void k_deg(const int* __restrict__ dst, const float* __restrict__ h,
                      float2* __restrict__ scal, int e_n, int n, int gEblocks) {
    if ((int)blockIdx.x < gEblocks) {
        int e = blockIdx.x * 256 + threadIdx.x;
        if (e < NHC * 65536) ((unsigned*)d_hist)[e] = 0;
        if (e < e_n) atomicAdd(&d_sb.deg[dst[e]], 1);
    } else {
        int node = (blockIdx.x - gEblocks) * 8 + (threadIdx.x >> 5);
        int t = threadIdx.x & 31;
        if (node >= n) return;
        float v = h[node * DIN + t];
        float sq = v * v;
        #pragma unroll
        for (int o = 16; o; o >>= 1) sq += __shfl_xor_sync(0xFFFFFFFFu, sq, o);
        float l2 = fmaxf(sqrtf(sq), 1e-12f);
        if (t == 0) scal[node].y = 1.0f / l2;
    }
}

// single-kernel exclusive scan via decoupled lookback; also writes norm + scal0.x
__global__ void k_scan(float2* __restrict__ scal, int n) {
    int bid = blockIdx.x;
    int i = bid * 1024 + threadIdx.x;
    int lane = threadIdx.x & 31, wid = threadIdx.x >> 5;
    int v = (i < n) ? d_sb.deg[i] : 0;
    int incl = v;
    #pragma unroll
    for (int o = 1; o < 32; o <<= 1) {
        int t = __shfl_up_sync(0xFFFFFFFFu, incl, o);
        if (lane >= o) incl += t;
    }
    __shared__ int ws[32];
    __shared__ int s_prefix, s_total;
    if (lane == 31) ws[wid] = incl;
    __syncthreads();
    if (wid == 0) {
        int wv = ws[lane];
        int wi = wv;
        #pragma unroll
        for (int o = 1; o < 32; o <<= 1) {
            int t = __shfl_up_sync(0xFFFFFFFFu, wi, o);
            if (lane >= o) wi += t;
        }
        ws[lane] = wi - wv;
        if (lane == 31) s_total = wi;
    }
    __syncthreads();
    int total = s_total;
    if (threadIdx.x == 0) {
        unsigned long long flag = (bid == 0) ? 2ull : 1ull;
        atomicExch(&d_sb.state[bid], (flag << 62) | (unsigned long long)(unsigned)total);
        int prefix = 0;
        if (bid > 0) {
            int j = bid - 1;
            while (1) {
                unsigned long long sf;
                do { sf = atomicAdd(&d_sb.state[j], 0ull); } while ((sf >> 62) == 0);
                prefix += (int)(unsigned)(sf & 0xFFFFFFFFull);
                if ((sf >> 62) == 2ull) break;
                j--;
            }
            atomicExch(&d_sb.state[bid], (2ull << 62) | (unsigned long long)(unsigned)(prefix + total));
        }
        s_prefix = prefix;
    }
    __syncthreads();
    int ex = s_prefix + ws[wid] + incl - v;
    if (i < n) {
        d_off[i] = ex;
        d_cur[i] = ex;
        float nv = rsqrtf((float)(v < 1 ? 1 : v));
        d_norm[i] = nv;
        scal[i].x = nv;
    }
    if (i == n - 1) d_off[n] = ex + v;
}

// pure CSR scatter
__global__ void k_build(const int* __restrict__ src, const int* __restrict__ dst, int e_n) {
    int e = blockIdx.x * 256 + threadIdx.x;
    if (e < e_n) {
        int d = dst[e];
        int p = atomicAdd(&d_cur[d], 1);
        d_csr_src[p] = src[e];
        d_csr_eid[p] = e;
    }
}

// ---------------- hop kernels ----------------

// fused cosine keys + privatized hist + full (uncut) propagation sum.
// FROZEN: measured optimum at 48 regs; do not restructure.
// NOTE: hout must NOT alias hin (gathered at arbitrary indices).
__global__ void k_cossum(const float* __restrict__ hin, const float2* __restrict__ scal,
                         float* __restrict__ hout, int n) {
    int node = blockIdx.x * 8 + (threadIdx.x >> 5);
    int t = threadIdx.x & 31;
    if (node >= n) return;
    int lane = t, g = t >> 3, sub = t & 7;
    const float4* h4 = (const float4*)hin;
    float4 drow = h4[node * 8 + sub];
    float2 sd = __ldg(&scal[node]);
    int b = d_off[node], e2 = d_off[node + 1];
    int deg = e2 - b;
    int myidx = (t < deg) ? __ldg(&d_csr_src[b + t]) : 0;
    unsigned* hist = d_hist[blockIdx.x & (NHC - 1)];
    float4 acc = make_float4(0.f, 0.f, 0.f, 0.f);
    int nb32 = deg < 32 ? deg : 32;
    for (int j0 = 0; j0 < nb32; j0 += 8) {
        int jA = j0 + g, jB = j0 + 4 + g;
        bool vA = jA < nb32, vB = jB < nb32;
        int sA = __shfl_sync(0xFFFFFFFFu, myidx, jA & 31);
        int sB = __shfl_sync(0xFFFFFFFFu, myidx, jB & 31);
        float4 aA = make_float4(0.f,0.f,0.f,0.f), aB = make_float4(0.f,0.f,0.f,0.f);
        float2 cA = make_float2(0.f,0.f), cB = make_float2(0.f,0.f);
        if (vA) { cA = __ldg(&scal[sA]); aA = h4[sA * 8 + sub]; }
        if (vB) { cB = __ldg(&scal[sB]); aB = h4[sB * 8 + sub]; }
        float pA = aA.x * drow.x + aA.y * drow.y + aA.z * drow.z + aA.w * drow.w;
        float pB = aB.x * drow.x + aB.y * drow.y + aB.z * drow.z + aB.w * drow.w;
        acc.x += cA.x * aA.x + cB.x * aB.x;
        acc.y += cA.x * aA.y + cB.x * aB.y;
        acc.z += cA.x * aA.z + cB.x * aB.z;
        acc.w += cA.x * aA.w + cB.x * aB.w;
        #pragma unroll
        for (int o = 1; o <= 4; o <<= 1) {
            pA += __shfl_xor_sync(0xFFFFFFFFu, pA, o);
            pB += __shfl_xor_sync(0xFFFFFFFFu, pB, o);
        }
        unsigned key = 0;
        bool haveKey = false;
        if (sub == 0 && vA) {
            float cos = pA * cA.y * sd.y;
            unsigned bits = __float_as_uint(cos);
            key = (bits & 0x80000000u) ? ~bits : (bits | 0x80000000u);
            d_keys[b + jA] = key;
            haveKey = true;
        }
        if (sub == 4 && vB) {
            float cos = pB * cB.y * sd.y;
            unsigned bits = __float_as_uint(cos);
            key = (bits & 0x80000000u) ? ~bits : (bits | 0x80000000u);
            d_keys[b + jB] = key;
            haveKey = true;
        }
        unsigned m = __ballot_sync(0xFFFFFFFFu, haveKey);
        if (haveKey) {
            unsigned bk = key >> 16;
            unsigned pm = __match_any_sync(m, bk);
            if ((int)(__ffs(pm) - 1) == lane) atomicAdd(&hist[bk], __popc(pm));
        }
    }
    // rare tail: deg > 32
    for (int k0 = b + 32; k0 < e2; k0 += 4) {
        int k = k0 + g;
        bool v = k < e2;
        int s = v ? __ldg(&d_csr_src[k]) : 0;
        float4 a = make_float4(0.f,0.f,0.f,0.f);
        float2 c = make_float2(0.f,0.f);
        if (v) { c = __ldg(&scal[s]); a = h4[s * 8 + sub]; }
        float p = a.x * drow.x + a.y * drow.y + a.z * drow.z + a.w * drow.w;
        acc.x += c.x * a.x; acc.y += c.x * a.y; acc.z += c.x * a.z; acc.w += c.x * a.w;
        #pragma unroll
        for (int o = 1; o <= 4; o <<= 1) p += __shfl_xor_sync(0xFFFFFFFFu, p, o);
        if (sub == 0 && v) {
            float cos = p * c.y * sd.y;
            unsigned bits = __float_as_uint(cos);
            unsigned key = (bits & 0x80000000u) ? ~bits : (bits | 0x80000000u);
            d_keys[k] = key;
            atomicAdd(&hist[key >> 16], 1u);
        }
    }
    #pragma unroll
    for (int o = 8; o <= 16; o <<= 1) {
        acc.x += __shfl_xor_sync(0xFFFFFFFFu, acc.x, o);
        acc.y += __shfl_xor_sync(0xFFFFFFFFu, acc.y, o);
        acc.z += __shfl_xor_sync(0xFFFFFFFFu, acc.z, o);
        acc.w += __shfl_xor_sync(0xFFFFFFFFu, acc.w, o);
    }
    if (g == 0) {
        float nv = sd.x;
        ((float4*)hout)[node * 8 + sub] =
            make_float4(nv * acc.x, nv * acc.y, nv * acc.z, nv * acc.w);
    }
}

// distributed bucket selection: NSEL blocks sum hist copies; last block finishes.
__global__ void k_select0(unsigned kcut) {
    __shared__ unsigned ws[32];
    __shared__ unsigned s_isLast;
    int tid = threadIdx.x;
    int bid = blockIdx.x;
    int bin = bid * 1024 + tid;
    int lane = tid & 31, wid = tid >> 5;

    unsigned s = 0;
    #pragma unroll
    for (int c = 0; c < NHC; c++) s += d_hist[c][bin];
    d_binsum[bin] = s;

    unsigned r = s;
    #pragma unroll
    for (int o = 16; o; o >>= 1) r += __shfl_xor_sync(0xFFFFFFFFu, r, o);
    if (lane == 0) ws[wid] = r;
    __syncthreads();
    if (wid == 0) {
        unsigned q = ws[lane];
        #pragma unroll
        for (int o = 16; o; o >>= 1) q += __shfl_xor_sync(0xFFFFFFFFu, q, o);
        if (lane == 0) {
            d_rangeTot[bid] = q;
            __threadfence();
            unsigned c = atomicAdd(&d_sb.finCount, 1u);
            s_isLast = (c == NSEL - 1) ? 1u : 0u;
        }
    }
    __syncthreads();
    if (!s_isLast) return;

    if (tid == 0) d_sb.finCount = 0;
    __shared__ unsigned rt[NSEL];
    __shared__ int s_range;
    __shared__ unsigned s_target;
    if (tid < NSEL) rt[tid] = d_rangeTot[tid];
    __syncthreads();
    if (tid == 0) {
        unsigned cum = 0;
        for (int q = 0; q < NSEL; q++) {
            unsigned v = rt[q];
            if (kcut <= cum + v) { s_range = q; s_target = kcut - cum; break; }
            cum += v;
        }
    }
    __syncthreads();
    int rng = s_range;
    unsigned target = s_target;
    unsigned v = d_binsum[rng * 1024 + tid];
    unsigned incl = v;
    #pragma unroll
    for (int o = 1; o < 32; o <<= 1) {
        unsigned x = __shfl_up_sync(0xFFFFFFFFu, incl, o);
        if (lane >= o) incl += x;
    }
    __syncthreads();
    if (lane == 31) ws[wid] = incl;
    __syncthreads();
    if (wid == 0) {
        unsigned wv = ws[lane];
        unsigned wi = wv;
        #pragma unroll
        for (int o = 1; o < 32; o <<= 1) {
            unsigned x = __shfl_up_sync(0xFFFFFFFFu, wi, o);
            if (lane >= o) wi += x;
        }
        ws[lane] = wi - wv;
    }
    __syncthreads();
    unsigned inclT = ws[wid] + incl;
    unsigned exclT = inclT - v;
    if (v > 0 && exclT < target && target <= inclT) {
        d_sb.bucket = (unsigned)(rng * 1024 + tid);
        d_sb.R1 = target - exclT;
    }
}

// coalesced weight write + warp-aggregated candidate collection.
// ZERO_HIST: re-zero the privatized hists for the next hop (skip on last hop).
template <bool ZERO_HIST>
__global__ void k_markc(int e_n) {
    int k = blockIdx.x * blockDim.x + threadIdx.x;
    if (ZERO_HIST && k < NHC * 65536) ((unsigned*)d_hist)[k] = 0;
    if (k >= e_n) return;
    unsigned key = d_keys[k];
    unsigned bkt = key >> 16;
    unsigned B = d_sb.bucket;
    d_wc[k] = (bkt < B) ? 0 : 1;
    bool cand = (bkt == B);
    unsigned m = __ballot_sync(0xFFFFFFFFu, cand);
    if (cand) {
        int lane = threadIdx.x & 31;
        int leader = __ffs(m) - 1;
        unsigned base = 0;
        if (lane == leader) base = atomicAdd(&d_sb.candCount, (unsigned)__popc(m));
        base = __shfl_sync(m, base, leader);
        unsigned q = base + __popc(m & ((1u << lane) - 1u));
        if (q < NCAND) {
            d_candKey[q] = (unsigned short)(key & 0xFFFFu);
            d_candEid[q] = d_csr_eid[k];
            d_candPos[q] = k;
        }
    }
}

// exact selection among candidates: 8+8 bit radix + deterministic eid tie-break
__global__ void k_fselect() {
    __shared__ unsigned hA[256], hB[256];
    __shared__ int s_b1, s_Rp, s_b0, s_Rpp;
    __shared__ int s_tieEid[NTIE], s_tiePos[NTIE];
    __shared__ unsigned s_tcnt;
    int tid = threadIdx.x;
    unsigned M = d_sb.candCount; if (M > NCAND) M = NCAND;
    unsigned R = d_sb.R1;
    for (int i = tid; i < 256; i += 1024) { hA[i] = 0; hB[i] = 0; }
    if (tid == 0) s_tcnt = 0;
    __syncthreads();
    for (unsigned i = tid; i < M; i += 1024)
        atomicAdd(&hA[d_candKey[i] >> 8], 1u);
    __syncthreads();
    if (tid == 0) {
        unsigned cum = 0;
        for (int k = 0; k < 256; k++) {
            unsigned v = hA[k];
            if (R <= cum + v) { s_b1 = k; s_Rp = (int)(R - cum); break; }
            cum += v;
        }
    }
    __syncthreads();
    unsigned b1 = (unsigned)s_b1;
    for (unsigned i = tid; i < M; i += 1024) {
        unsigned kk = d_candKey[i];
        if ((kk >> 8) == b1) atomicAdd(&hB[kk & 0xFFu], 1u);
    }
    __syncthreads();
    if (tid == 0) {
        unsigned cum = 0, Rp = (unsigned)s_Rp;
        for (int k = 0; k < 256; k++) {
            unsigned v = hB[k];
            if (Rp <= cum + v) { s_b0 = k; s_Rpp = (int)(Rp - cum); break; }
            cum += v;
        }
    }
    __syncthreads();
    unsigned Tlow = (b1 << 8) | (unsigned)s_b0;
    for (unsigned i = tid; i < M; i += 1024) {
        unsigned kk = d_candKey[i];
        if (kk < Tlow) d_wc[d_candPos[i]] = 0;
        else if (kk == Tlow) {
            unsigned q = atomicAdd(&s_tcnt, 1u);
            if (q < NTIE) { s_tieEid[q] = d_candEid[i]; s_tiePos[q] = d_candPos[i]; }
        }
    }
    __syncthreads();
    unsigned tc = s_tcnt; if (tc > NTIE) tc = NTIE;
    unsigned Rpp = (unsigned)s_Rpp;
    for (unsigned i = tid; i < tc; i += 1024) {
        int ei = s_tieEid[i];
        unsigned rank = 0;
        for (unsigned j = 0; j < tc; j++) rank += (unsigned)(s_tieEid[j] < ei);
        if (rank < Rpp) d_wc[s_tiePos[i]] = 0;
    }
    if (tid == 0) d_sb.candCount = 0;
}

// subtract cut-edge contributions; optionally emit next hop's scal
template <bool WRITE_SCAL>
__global__ void k_correct(float* __restrict__ h_io, const float* __restrict__ h_in,
                          const float2* __restrict__ scal_in, float2* __restrict__ scal_out,
                          int n) {
    int node = blockIdx.x * 8 + (threadIdx.x >> 5);
    int t = threadIdx.x & 31;
    if (node >= n) return;
    int g = t >> 3, sub = t & 7;
    int b = d_off[node], e2 = d_off[node + 1];
    const float4* h4 = (const float4*)h_in;
    float4 acc = make_float4(0.f, 0.f, 0.f, 0.f);
    for (int base = b; base < e2; base += 32) {
        int idx = base + t;
        unsigned char w = (idx < e2) ? d_wc[idx] : 1;
        unsigned m = __ballot_sync(0xFFFFFFFFu, w == 0);
        int nc = __popc(m);
        for (int q = g; q < nc; q += 4) {
            int j = (int)__fns(m, 0, q + 1);
            int k = base + j;
            int s = __ldg(&d_csr_src[k]);
            float c = __ldg(&scal_in[s]).x;
            float4 a = h4[s * 8 + sub];
            acc.x += c * a.x; acc.y += c * a.y; acc.z += c * a.z; acc.w += c * a.w;
        }
    }
    #pragma unroll
    for (int o = 8; o <= 16; o <<= 1) {
        acc.x += __shfl_xor_sync(0xFFFFFFFFu, acc.x, o);
        acc.y += __shfl_xor_sync(0xFFFFFFFFu, acc.y, o);
        acc.z += __shfl_xor_sync(0xFFFFFFFFu, acc.z, o);
        acc.w += __shfl_xor_sync(0xFFFFFFFFu, acc.w, o);
    }
    float nv = d_norm[node];
    float4 hv = make_float4(0.f, 0.f, 0.f, 0.f);
    if (g == 0) {
        hv = ((float4*)h_io)[node * 8 + sub];
        hv.x -= nv * acc.x; hv.y -= nv * acc.y; hv.z -= nv * acc.z; hv.w -= nv * acc.w;
        ((float4*)h_io)[node * 8 + sub] = hv;
    }
    if (WRITE_SCAL) {
        float sq = (g == 0) ? (hv.x*hv.x + hv.y*hv.y + hv.z*hv.z + hv.w*hv.w) : 0.f;
        #pragma unroll
        for (int o = 1; o <= 4; o <<= 1) sq += __shfl_xor_sync(0xFFFFFFFFu, sq, o);
        float l2 = fmaxf(sqrtf(sq), 1e-12f);
        if (t == 0) scal_out[node] = make_float2(nv, 1.0f / l2);
    }
}

__global__ void k_fc(const float* __restrict__ h, const float* __restrict__ W,
                     float* __restrict__ out, int n) {
    __shared__ float sW[DIN * DOUT];
    __shared__ float sh[16 * DIN];
    for (int i = threadIdx.x; i < DIN * DOUT; i += blockDim.x) {
        int j = i >> 5, t = i & 31;
        sW[t * DOUT + j] = W[i];
    }
    int row0 = blockIdx.x * 16;
    for (int i = threadIdx.x; i < 16 * DIN; i += blockDim.x) {
        int r = row0 + (i >> 5);
        sh[i] = (r < n) ? h[row0 * DIN + i] : 0.0f;
    }
    __syncthreads();
    int r = threadIdx.x >> 6;
    int j = threadIdx.x & 63;
    int row = row0 + r;
    if (row >= n) return;
    float acc = 0.0f;
    #pragma unroll
    for (int t = 0; t < DIN; t++) acc += sh[r * DIN + t] * sW[t * DOUT + j];
    out[row * DOUT + j] = acc;
}

// ---------------- launch ----------------

extern "C" void kernel_launch(void* const* d_in, const int* in_sizes, int n_in,
                              void* d_out, int out_size) {
    const float* features = (const float*)d_in[0];
    const int*   src      = (const int*)d_in[1];
    const int*   dst      = (const int*)d_in[2];
    const float* W        = (const float*)d_in[3];
    float* out = (float*)d_out;

    int n = in_sizes[0] / DIN;
    int e = in_sizes[1];
    if (n > NN) n = NN;
    if (e > EE) e = EE;
    unsigned kcut = (unsigned)((long long)e / 10);

    void *p_sb, *p_hA, *p_hB, *p_s0, *p_s1;
    cudaGetSymbolAddress(&p_sb, d_sb);
    cudaGetSymbolAddress(&p_hA, d_hA);
    cudaGetSymbolAddress(&p_hB, d_hB);
    cudaGetSymbolAddress(&p_s0, d_scal0);
    cudaGetSymbolAddress(&p_s1, d_scal1);

    float* hA = (float*)p_hA;
    float* hB = (float*)p_hB;
    float2* s0 = (float2*)p_s0;
    float2* s1 = (float2*)p_s1;

    int gE  = (e + 255) / 256;
    int gNw = (n + 7) / 8;
    int nb  = (n + 1023) / 1024;

    cudaMemsetAsync(p_sb, 0, sizeof(SelBlock));
    k_deg<<<gE + gNw, 256>>>(dst, features, s0, e, n, gE);
    k_scan<<<nb, 1024>>>(s0, n);
    k_build<<<gE, 256>>>(src, dst, e);

    // hop 0 (k_cossum stays in profiled slot 5)
    k_cossum<<<gNw, 256>>>(features, s0, hA, n);
    k_select0<<<NSEL, 1024>>>(kcut);
    k_markc<true><<<gE, 256>>>(e);
    k_fselect<<<1, 1024>>>();
    k_correct<true><<<gNw, 256>>>(hA, features, s0, s1, n);

    // hop 1 (no hist re-zero needed after the final select)
    k_cossum<<<gNw, 256>>>(hA, s1, hB, n);
    k_select0<<<NSEL, 1024>>>(kcut);
    k_markc<false><<<gE, 256>>>(e);
    k_fselect<<<1, 1024>>>();
    k_correct<false><<<gNw, 256>>>(hB, hA, s1, nullptr, n);

    k_fc<<<(n + 15) / 16, 1024>>>(hB, W, out, n);
}